// round 2
// baseline (speedup 1.0000x reference)
#include <cuda_runtime.h>
#include <cstdint>

// Problem constants
#define G      8
#define VCODES 512
#define HDIM   128
#define NTOK   16384          // B*T = 8*2048
#define TILE_N 64
#define TILE_V 128
#define XS_STRIDE 68          // 64 + 4 pad (keeps 16B row alignment)
#define ES_STRIDE 132         // 128 + 4 pad
#define SMEM_FLOATS (HDIM*XS_STRIDE + HDIM*ES_STRIDE)   // 25600 floats = 100 KB

// Scratch (device globals: no allocation allowed)
__device__ int   g_codes[G * NTOK];
__device__ float g_enorm[G * VCODES];

// ---------------------------------------------------------------------------
// Kernel 0: ||e||^2 per (g, code). 4096 rows of 128 floats.
// ---------------------------------------------------------------------------
__global__ void pq_enorm_kernel(const float* __restrict__ embed) {
    const int row  = blockIdx.x * 8 + (threadIdx.x >> 5);
    const int lane = threadIdx.x & 31;
    const float* e = embed + (size_t)row * HDIM;
    const float v0 = e[lane], v1 = e[lane + 32], v2 = e[lane + 64], v3 = e[lane + 96];
    float s = v0 * v0 + v1 * v1 + v2 * v2 + v3 * v3;
    #pragma unroll
    for (int off = 16; off; off >>= 1) s += __shfl_xor_sync(0xffffffffu, s, off);
    if (lane == 0) g_enorm[row] = s;
}

// ---------------------------------------------------------------------------
// Kernel 1: per (g, token) argmin over 512 codes of ||e||^2 - 2*x.e
// CTA = (64 tokens, 1 group). 256 threads = 8 warps.
// warp w owns tokens [w*8, w*8+8); lane owns 4 codes per 128-code chunk.
// Inner product via packed fp32 FFMA2 (fma.rn.f32x2).
// ---------------------------------------------------------------------------
#define FMA2(ACC, XP, ED) \
    asm("fma.rn.f32x2 %0, %1, %2, %0;" : "+l"(ACC) : "l"(XP), "l"(ED))

__global__ __launch_bounds__(256, 2) void pq_argmin_kernel(
    const float* __restrict__ x, const float* __restrict__ embed)
{
    extern __shared__ float smem[];
    float* xs = smem;                        // [HDIM][XS_STRIDE]  x transposed
    float* es = smem + HDIM * XS_STRIDE;     // [HDIM][ES_STRIDE]  embed chunk transposed

    const int g    = blockIdx.y;
    const int n0   = blockIdx.x * TILE_N;
    const int tid  = threadIdx.x;
    const int lane = tid & 31;
    const int w    = tid >> 5;

    // ---- load x tile transposed: xs[k][t]  (warp-broadcast-friendly reads) ----
    for (int t = w; t < TILE_N; t += 8) {
        const float4 v = *reinterpret_cast<const float4*>(
            x + (size_t)(n0 + t) * (G * HDIM) + (g * HDIM) + (lane << 2));
        const int k4 = lane << 2;
        xs[(k4 + 0) * XS_STRIDE + t] = v.x;
        xs[(k4 + 1) * XS_STRIDE + t] = v.y;
        xs[(k4 + 2) * XS_STRIDE + t] = v.z;
        xs[(k4 + 3) * XS_STRIDE + t] = v.w;
    }

    float best[8];
    int   bidx[8];
    #pragma unroll
    for (int t = 0; t < 8; t++) { best[t] = 3.4e38f; bidx[t] = 0; }

    const unsigned xs_base = (unsigned)__cvta_generic_to_shared(xs) + (w << 5);
    const unsigned es_base = (unsigned)__cvta_generic_to_shared(es) + (lane << 4);

    for (int v0 = 0; v0 < VCODES; v0 += TILE_V) {
        __syncthreads();   // previous chunk fully consumed

        // ---- fill es[k][c] transposed; STS conflict-free (consecutive c per lane) ----
        #pragma unroll
        for (int cg = 0; cg < 4; cg++) {
            const int c = (cg << 5) + lane;
            const float4* src = reinterpret_cast<const float4*>(
                embed + ((size_t)(g * VCODES) + v0 + c) * HDIM);
            #pragma unroll
            for (int s = 0; s < 4; s++) {
                const int k4 = (w << 4) + (s << 2);
                const float4 v = src[k4 >> 2];
                es[(k4 + 0) * ES_STRIDE + c] = v.x;
                es[(k4 + 1) * ES_STRIDE + c] = v.y;
                es[(k4 + 2) * ES_STRIDE + c] = v.z;
                es[(k4 + 3) * ES_STRIDE + c] = v.w;
            }
        }

        float en[4];
        {
            const float* ep = g_enorm + g * VCODES + v0 + (lane << 2);
            en[0] = ep[0]; en[1] = ep[1]; en[2] = ep[2]; en[3] = ep[3];
        }
        __syncthreads();

        // ---- 64x128x128 chunk GEMM fragment: 8 tokens x 4 codes per thread ----
        uint64_t acc[4][4];
        #pragma unroll
        for (int a = 0; a < 4; a++)
            #pragma unroll
            for (int b = 0; b < 4; b++) acc[a][b] = 0ull;

        unsigned xa = xs_base, ea = es_base;
        #pragma unroll 4
        for (int k = 0; k < HDIM; k++) {
            uint64_t x01, x23, x45, x67;
            // token pairs come pre-packed from adjacent SMEM floats
            asm volatile("ld.shared.v2.b64 {%0,%1}, [%2];"
                         : "=l"(x01), "=l"(x23) : "r"(xa));
            asm volatile("ld.shared.v2.b64 {%0,%1}, [%2];"
                         : "=l"(x45), "=l"(x67) : "r"(xa + 16));
            unsigned e0, e1, e2, e3;
            asm volatile("ld.shared.v4.b32 {%0,%1,%2,%3}, [%4];"
                         : "=r"(e0), "=r"(e1), "=r"(e2), "=r"(e3) : "r"(ea));
            uint64_t d0, d1, d2, d3;  // duplicate each code value into both halves
            asm("mov.b64 %0, {%1,%1};" : "=l"(d0) : "r"(e0));
            asm("mov.b64 %0, {%1,%1};" : "=l"(d1) : "r"(e1));
            asm("mov.b64 %0, {%1,%1};" : "=l"(d2) : "r"(e2));
            asm("mov.b64 %0, {%1,%1};" : "=l"(d3) : "r"(e3));

            FMA2(acc[0][0], x01, d0); FMA2(acc[0][1], x01, d1);
            FMA2(acc[0][2], x01, d2); FMA2(acc[0][3], x01, d3);
            FMA2(acc[1][0], x23, d0); FMA2(acc[1][1], x23, d1);
            FMA2(acc[1][2], x23, d2); FMA2(acc[1][3], x23, d3);
            FMA2(acc[2][0], x45, d0); FMA2(acc[2][1], x45, d1);
            FMA2(acc[2][2], x45, d2); FMA2(acc[2][3], x45, d3);
            FMA2(acc[3][0], x67, d0); FMA2(acc[3][1], x67, d1);
            FMA2(acc[3][2], x67, d2); FMA2(acc[3][3], x67, d3);

            xa += XS_STRIDE * 4;
            ea += ES_STRIDE * 4;
        }

        // ---- fold chunk scores into running per-token best ----
        const int cbase = v0 + (lane << 2);
        #pragma unroll
        for (int tp = 0; tp < 4; tp++) {
            #pragma unroll
            for (int j = 0; j < 4; j++) {
                const uint64_t a = acc[tp][j];
                const float lo = __uint_as_float((unsigned)(a & 0xffffffffu));
                const float hi = __uint_as_float((unsigned)(a >> 32));
                const float s0 = fmaf(-2.f, lo, en[j]);
                const float s1 = fmaf(-2.f, hi, en[j]);
                const int idx = cbase + j;
                if (s0 < best[2 * tp])     { best[2 * tp]     = s0; bidx[2 * tp]     = idx; }
                if (s1 < best[2 * tp + 1]) { best[2 * tp + 1] = s1; bidx[2 * tp + 1] = idx; }
            }
        }
    }

    // ---- warp-level argmin across lanes (lowest index wins ties) ----
    #pragma unroll
    for (int t = 0; t < 8; t++) {
        float s = best[t]; int b = bidx[t];
        #pragma unroll
        for (int off = 16; off; off >>= 1) {
            const float so = __shfl_xor_sync(0xffffffffu, s, off);
            const int   bo = __shfl_xor_sync(0xffffffffu, b, off);
            if (so < s || (so == s && bo < b)) { s = so; b = bo; }
        }
        if (lane == 0) g_codes[g * NTOK + n0 + w * 8 + t] = b;
    }
}

// ---------------------------------------------------------------------------
// Kernel 2: gather quantized output. quant[n][g*128+h] = embed[g][code][h].
// float4-granular; each warp handles one (n,g) row -> broadcast code load,
// coalesced 512B embed row (L2-resident).
// ---------------------------------------------------------------------------
__global__ void pq_gather_kernel(const float* __restrict__ embed,
                                 float4* __restrict__ outq) {
    const int i  = blockIdx.x * blockDim.x + threadIdx.x;  // over 4,194,304 float4s
    const int h4 = i & 31;
    const int gg = (i >> 5) & 7;
    const int n  = i >> 8;
    const int c  = g_codes[gg * NTOK + n];
    outq[i] = reinterpret_cast<const float4*>(embed)[((gg << 9) + c) * 32 + h4];
}

// Kernel 3: codes output as float, layout (n, g).
__global__ void pq_codes_kernel(float* __restrict__ outc) {
    const int i = blockIdx.x * blockDim.x + threadIdx.x;   // 131072
    outc[i] = (float)g_codes[(i & 7) * NTOK + (i >> 3)];
}

// ---------------------------------------------------------------------------
extern "C" void kernel_launch(void* const* d_in, const int* in_sizes, int n_in,
                              void* d_out, int out_size) {
    const float* x     = (const float*)d_in[0];
    const float* embed = (const float*)d_in[1];
    float* out = (float*)d_out;

    cudaFuncSetAttribute(pq_argmin_kernel,
                         cudaFuncAttributeMaxDynamicSharedMemorySize,
                         SMEM_FLOATS * 4);

    pq_enorm_kernel<<<512, 256>>>(embed);
    pq_argmin_kernel<<<dim3(NTOK / TILE_N, G), 256, SMEM_FLOATS * 4>>>(x, embed);
    pq_gather_kernel<<<(NTOK * G * HDIM / 4) / 256, 256>>>(embed, (float4*)out);
    pq_codes_kernel<<<(NTOK * G) / 256, 256>>>(out + (size_t)NTOK * G * HDIM);
}